// round 1
// baseline (speedup 1.0000x reference)
#include <cuda_runtime.h>

// Problem constants (fixed shapes)
#define Bx 8
#define Tt 2048
#define Dd 256
#define NR (Bx*Tt)            // 16384 rows
#define EPSF 1e-8f

// ---------------- scratch (device globals; no runtime allocation) ----------
__device__ float g_v1[(size_t)NR*Dd];
__device__ float g_v2[(size_t)NR*Dd];
__device__ float g_a1[(size_t)NR*Dd];
__device__ float g_a2[(size_t)NR*Dd];
__device__ float g_beta[(size_t)Bx*Tt*Tt];   // 134 MB
__device__ float g_R[Bx*Tt];       // row sums of beta
__device__ float g_Cc[Bx*Tt];      // col sums of beta
__device__ float g_SmC[Bx*Tt];     // masked col sums (atomic accum)
__device__ float g_thrR[Bx*Tt];
__device__ float g_scaleR[Bx*Tt];
__device__ float g_thrC[Bx*Tt];
__device__ float g_scaleC[Bx*Tt];
__device__ float g_apos[(size_t)NR*Dd];
__device__ float g_vpos[(size_t)NR*Dd];
__device__ float g_zv[(size_t)NR*Dd];
__device__ float g_za[(size_t)NR*Dd];

// ---------------- helpers ---------------------------------------------------
__device__ __forceinline__ void mm_tile_16(const float Xs[16][64], const float Ws[16][64],
                                           float acc[4][4], int tx, int ty) {
#pragma unroll
    for (int kk = 0; kk < 16; kk++) {
        float4 a4 = *reinterpret_cast<const float4*>(&Xs[kk][ty*4]);
        float4 b4 = *reinterpret_cast<const float4*>(&Ws[kk][tx*4]);
        float a[4] = {a4.x, a4.y, a4.z, a4.w};
        float b[4] = {b4.x, b4.y, b4.z, b4.w};
#pragma unroll
        for (int i = 0; i < 4; i++)
#pragma unroll
            for (int j = 0; j < 4; j++) acc[i][j] += a[i]*b[j];
    }
}

// ---------------- init: zero accumulators -----------------------------------
__global__ void init_kernel() {
    int idx = blockIdx.x*256 + threadIdx.x;
    if (idx < Bx*Tt) { g_R[idx] = 0.f; g_Cc[idx] = 0.f; g_SmC[idx] = 0.f; }
}

// ---------------- K1: 4 projection GEMMs + ReLU ------------------------------
// C[n,h] = relu(sum_d X[n,d] * W[h,d]);  M=16384, N=256, K=256
__global__ void proj_kernel(const float* __restrict__ v_fea, const float* __restrict__ a_fea,
                            const float* __restrict__ Wv1, const float* __restrict__ Wv2,
                            const float* __restrict__ Wa1, const float* __restrict__ Wa2) {
    int which = blockIdx.z;
    const float* X = (which < 2) ? v_fea : a_fea;
    const float* W = (which == 0) ? Wv1 : (which == 1) ? Wv2 : (which == 2) ? Wa1 : Wa2;
    float* Cout = (which == 0) ? g_v1 : (which == 1) ? g_v2 : (which == 2) ? g_a1 : g_a2;

    __shared__ float Xs[16][64];
    __shared__ float Ws[16][64];
    int bm = blockIdx.y*64, bn = blockIdx.x*64;
    int tid = threadIdx.x, tx = tid % 16, ty = tid / 16;
    float acc[4][4] = {};
    for (int k0 = 0; k0 < Dd; k0 += 16) {
#pragma unroll
        for (int r = 0; r < 4; r++) {
            int kk = tid % 16, mm = tid / 16 + r*16;
            Xs[kk][mm] = X[(size_t)(bm+mm)*Dd + k0 + kk];
            Ws[kk][mm] = W[(size_t)(bn+mm)*Dd + k0 + kk];
        }
        __syncthreads();
        mm_tile_16(Xs, Ws, acc, tx, ty);
        __syncthreads();
    }
#pragma unroll
    for (int i = 0; i < 4; i++) {
        float4 v;
        v.x = fmaxf(acc[i][0], 0.f); v.y = fmaxf(acc[i][1], 0.f);
        v.z = fmaxf(acc[i][2], 0.f); v.w = fmaxf(acc[i][3], 0.f);
        *reinterpret_cast<float4*>(&Cout[(size_t)(bm + ty*4 + i)*Dd + bn + tx*4]) = v;
    }
}

// ---------------- K2: score GEMM beta = relu(v2 @ a1^T / 16) + row/col sums --
__global__ void score_kernel() {
    int b = blockIdx.z;
    const float* V2 = g_v2 + (size_t)b*Tt*Dd;
    const float* A1 = g_a1 + (size_t)b*Tt*Dd;
    float* beta = g_beta + (size_t)b*Tt*Tt;

    __shared__ float Xs[16][64];
    __shared__ float Ws[16][64];
    __shared__ float srow[64], scol[64];
    int bm = blockIdx.y*64, bn = blockIdx.x*64;
    int tid = threadIdx.x, tx = tid % 16, ty = tid / 16;
    if (tid < 64) { srow[tid] = 0.f; scol[tid] = 0.f; }
    float acc[4][4] = {};
    for (int k0 = 0; k0 < Dd; k0 += 16) {
#pragma unroll
        for (int r = 0; r < 4; r++) {
            int kk = tid % 16, mm = tid / 16 + r*16;
            Xs[kk][mm] = V2[(size_t)(bm+mm)*Dd + k0 + kk];
            Ws[kk][mm] = A1[(size_t)(bn+mm)*Dd + k0 + kk];
        }
        __syncthreads();
        mm_tile_16(Xs, Ws, acc, tx, ty);
        __syncthreads();
    }
    float vals[4][4];
    float rsum[4] = {0,0,0,0}, csum[4] = {0,0,0,0};
#pragma unroll
    for (int i = 0; i < 4; i++)
#pragma unroll
        for (int j = 0; j < 4; j++) {
            float v = fmaxf(acc[i][j]*(1.f/16.f), 0.f);
            vals[i][j] = v; rsum[i] += v; csum[j] += v;
        }
#pragma unroll
    for (int i = 0; i < 4; i++) {
        float4 v = {vals[i][0], vals[i][1], vals[i][2], vals[i][3]};
        *reinterpret_cast<float4*>(&beta[(size_t)(bm + ty*4 + i)*Tt + bn + tx*4]) = v;
        atomicAdd(&srow[ty*4 + i], rsum[i]);
        atomicAdd(&scol[tx*4 + i], csum[i]);
    }
    __syncthreads();
    if (tid < 64) {
        atomicAdd(&g_R[b*Tt + bm + tid], srow[tid]);
        atomicAdd(&g_Cc[b*Tt + bn + tid], scol[tid]);
    }
}

// ---------------- K3a: per-row masked sums -> thrR, scaleR --------------------
__global__ void row_mask_kernel(const float* __restrict__ thr_p) {
    int row = blockIdx.x;                  // 0..16383 (b*T + i)
    const float* brow = g_beta + (size_t)row*Tt;
    float thr = thr_p[0] * 10.f / (float)Tt;
    float R = g_R[row];
    float cut = thr * (R + EPSF);
    float s = 0.f;
    for (int j = threadIdx.x; j < Tt; j += 256) {
        float v = brow[j];
        if (v > cut) s += v;
    }
#pragma unroll
    for (int o = 16; o > 0; o >>= 1) s += __shfl_down_sync(0xffffffffu, s, o);
    __shared__ float sh[8];
    if ((threadIdx.x & 31) == 0) sh[threadIdx.x >> 5] = s;
    __syncthreads();
    if (threadIdx.x == 0) {
        float t = 0.f;
#pragma unroll
        for (int w = 0; w < 8; w++) t += sh[w];
        g_thrR[row] = cut;
        g_scaleR[row] = 1.f / (t + EPSF*(R + EPSF));
    }
}

// ---------------- K3b: per-col masked partial sums ---------------------------
__global__ void col_partial_kernel(const float* __restrict__ thr_p) {
    int b = blockIdx.z;
    int j = blockIdx.x*256 + threadIdx.x;
    int i0 = blockIdx.y*256;
    float thr = thr_p[0] * 10.f / (float)Tt;
    float Cv = g_Cc[b*Tt + j];
    float cut = thr * (Cv + EPSF);
    const float* bb = g_beta + (size_t)b*Tt*Tt;
    float s = 0.f;
#pragma unroll 4
    for (int i = i0; i < i0 + 256; i++) {
        float v = bb[(size_t)i*Tt + j];
        if (v > cut) s += v;
    }
    atomicAdd(&g_SmC[b*Tt + j], s);
}

__global__ void col_finalize_kernel(const float* __restrict__ thr_p) {
    int idx = blockIdx.x*256 + threadIdx.x;
    if (idx < Bx*Tt) {
        float thr = thr_p[0] * 10.f / (float)Tt;
        float Cv = g_Cc[idx];
        float cut = thr * (Cv + EPSF);
        g_thrC[idx] = cut;
        g_scaleC[idx] = 1.f / (g_SmC[idx] + EPSF*(Cv + EPSF));
    }
}

// ---------------- pred: diag of g_av[0] > 0 ----------------------------------
__global__ void pred_kernel(float* __restrict__ out_pred) {
    int t = blockIdx.x*256 + threadIdx.x;   // 0..2047
    float v = g_beta[(size_t)t*Tt + t];     // batch 0
    out_pred[t] = (v > g_thrC[t]) ? 1.f : 0.f;
}

// ---------------- K4a: a_pos = g_va @ a2 (mask applied on the fly) -----------
__global__ void apply_va_kernel() {
    int b = blockIdx.z;
    const float* beta = g_beta + (size_t)b*Tt*Tt;
    const float* Bm = g_a2 + (size_t)b*Tt*Dd;
    float* out = g_apos + (size_t)b*Tt*Dd;
    __shared__ float As[16][64];
    __shared__ float Bs[16][64];
    __shared__ float sThr[64], sScale[64];
    int bm = blockIdx.y*64, bn = blockIdx.x*64;
    int tid = threadIdx.x, tx = tid % 16, ty = tid / 16;
    if (tid < 64) { sThr[tid] = g_thrR[b*Tt + bm + tid]; sScale[tid] = g_scaleR[b*Tt + bm + tid]; }
    __syncthreads();
    float acc[4][4] = {};
    for (int k0 = 0; k0 < Tt; k0 += 16) {
#pragma unroll
        for (int r = 0; r < 4; r++) {
            int kk = tid % 16, mm = tid / 16 + r*16;
            float v = beta[(size_t)(bm+mm)*Tt + k0 + kk];
            As[kk][mm] = (v > sThr[mm]) ? v * sScale[mm] : 0.f;
            int nn = tid % 64, k2 = tid / 64 + r*4;
            Bs[k2][nn] = Bm[(size_t)(k0+k2)*Dd + bn + nn];
        }
        __syncthreads();
        mm_tile_16(As, Bs, acc, tx, ty);
        __syncthreads();
    }
#pragma unroll
    for (int i = 0; i < 4; i++) {
        float4 v = {acc[i][0], acc[i][1], acc[i][2], acc[i][3]};
        *reinterpret_cast<float4*>(&out[(size_t)(bm + ty*4 + i)*Dd + bn + tx*4]) = v;
    }
}

// ---------------- K4b: v_pos = g_av @ v1 (A = masked beta^T) ------------------
__global__ void apply_av_kernel() {
    int b = blockIdx.z;
    const float* beta = g_beta + (size_t)b*Tt*Tt;
    const float* Bm = g_v1 + (size_t)b*Tt*Dd;
    float* out = g_vpos + (size_t)b*Tt*Dd;
    __shared__ float As[16][64];
    __shared__ float Bs[16][64];
    __shared__ float sThr[64], sScale[64];
    int bm = blockIdx.y*64, bn = blockIdx.x*64;
    int tid = threadIdx.x, tx = tid % 16, ty = tid / 16;
    if (tid < 64) { sThr[tid] = g_thrC[b*Tt + bm + tid]; sScale[tid] = g_scaleC[b*Tt + bm + tid]; }
    __syncthreads();
    float acc[4][4] = {};
    for (int k0 = 0; k0 < Tt; k0 += 16) {
#pragma unroll
        for (int r = 0; r < 4; r++) {
            int mm = tid % 64, kk = tid / 64 + r*4;   // transposed read, coalesced over mm
            float v = beta[(size_t)(k0+kk)*Tt + bm + mm];
            As[kk][mm] = (v > sThr[mm]) ? v * sScale[mm] : 0.f;
            int nn = tid % 64, k2 = tid / 64 + r*4;
            Bs[k2][nn] = Bm[(size_t)(k0+k2)*Dd + bn + nn];
        }
        __syncthreads();
        mm_tile_16(As, Bs, acc, tx, ty);
        __syncthreads();
    }
#pragma unroll
    for (int i = 0; i < 4; i++) {
        float4 v = {acc[i][0], acc[i][1], acc[i][2], acc[i][3]};
        *reinterpret_cast<float4*>(&out[(size_t)(bm + ty*4 + i)*Dd + bn + tx*4]) = v;
    }
}

// ---------------- K5: z = relu((X1 + X2) @ W^T) ------------------------------
__global__ void fc_kernel(const float* __restrict__ v_fea, const float* __restrict__ a_fea,
                          const float* __restrict__ Wvfc, const float* __restrict__ Wafc) {
    int which = blockIdx.z;       // 0: v branch, 1: a branch
    const float* X1 = (which == 0) ? v_fea : a_fea;
    const float* X2 = (which == 0) ? g_apos : g_vpos;
    const float* W  = (which == 0) ? Wvfc : Wafc;
    float* Cout     = (which == 0) ? g_zv : g_za;

    __shared__ float Xs[16][64];
    __shared__ float Ws[16][64];
    int bm = blockIdx.y*64, bn = blockIdx.x*64;
    int tid = threadIdx.x, tx = tid % 16, ty = tid / 16;
    float acc[4][4] = {};
    for (int k0 = 0; k0 < Dd; k0 += 16) {
#pragma unroll
        for (int r = 0; r < 4; r++) {
            int kk = tid % 16, mm = tid / 16 + r*16;
            size_t xi = (size_t)(bm+mm)*Dd + k0 + kk;
            Xs[kk][mm] = X1[xi] + X2[xi];
            Ws[kk][mm] = W[(size_t)(bn+mm)*Dd + k0 + kk];
        }
        __syncthreads();
        mm_tile_16(Xs, Ws, acc, tx, ty);
        __syncthreads();
    }
#pragma unroll
    for (int i = 0; i < 4; i++) {
        float4 v;
        v.x = fmaxf(acc[i][0], 0.f); v.y = fmaxf(acc[i][1], 0.f);
        v.z = fmaxf(acc[i][2], 0.f); v.w = fmaxf(acc[i][3], 0.f);
        *reinterpret_cast<float4*>(&Cout[(size_t)(bm + ty*4 + i)*Dd + bn + tx*4]) = v;
    }
}

// ---------------- K6: dual LayerNorm + fuse ----------------------------------
__global__ void ln_fuse_kernel(const float* __restrict__ ln_g, const float* __restrict__ ln_b,
                               float* __restrict__ out_fuse, float* __restrict__ out_vpsp,
                               float* __restrict__ out_apsp) {
    int row = blockIdx.x;          // 0..16383
    int tid = threadIdx.x;         // 0..255 == feature index
    float zv = g_zv[(size_t)row*Dd + tid];
    float za = g_za[(size_t)row*Dd + tid];
    float4 s = make_float4(zv, zv*zv, za, za*za);
#pragma unroll
    for (int o = 16; o > 0; o >>= 1) {
        s.x += __shfl_down_sync(0xffffffffu, s.x, o);
        s.y += __shfl_down_sync(0xffffffffu, s.y, o);
        s.z += __shfl_down_sync(0xffffffffu, s.z, o);
        s.w += __shfl_down_sync(0xffffffffu, s.w, o);
    }
    __shared__ float4 sh[8];
    __shared__ float4 stats;
    if ((tid & 31) == 0) sh[tid >> 5] = s;
    __syncthreads();
    if (tid == 0) {
        float4 t = sh[0];
#pragma unroll
        for (int w = 1; w < 8; w++) { t.x += sh[w].x; t.y += sh[w].y; t.z += sh[w].z; t.w += sh[w].w; }
        stats = t;
    }
    __syncthreads();
    float inv = 1.f / (float)Dd;
    float mv = stats.x * inv, mva = stats.z * inv;
    float varv = stats.y * inv - mv*mv;
    float vara = stats.w * inv - mva*mva;
    float g = ln_g[tid], bb = ln_b[tid];
    float vpsp = (zv - mv) * rsqrtf(varv + 1e-6f) * g + bb;
    float apsp = (za - mva) * rsqrtf(vara + 1e-6f) * g + bb;
    size_t o = (size_t)row*Dd + tid;
    out_vpsp[o] = vpsp;
    out_apsp[o] = apsp;
    out_fuse[o] = 0.5f * (vpsp + apsp);
}

// ---------------- launch ------------------------------------------------------
extern "C" void kernel_launch(void* const* d_in, const int* in_sizes, int n_in,
                              void* d_out, int out_size) {
    const float* a_fea = (const float*)d_in[0];
    const float* v_fea = (const float*)d_in[1];
    const float* thr_p = (const float*)d_in[2];
    const float* Wv1   = (const float*)d_in[3];
    const float* Wv2   = (const float*)d_in[4];
    const float* Wvfc  = (const float*)d_in[5];
    const float* Wa1   = (const float*)d_in[6];
    const float* Wa2   = (const float*)d_in[7];
    const float* Wafc  = (const float*)d_in[8];
    const float* ln_g  = (const float*)d_in[9];
    const float* ln_b  = (const float*)d_in[10];
    (void)in_sizes; (void)n_in; (void)out_size;

    float* out = (float*)d_out;
    float* out_fuse = out;
    float* out_vpsp = out + (size_t)NR*Dd;
    float* out_apsp = out + 2*(size_t)NR*Dd;
    float* out_pred = out + 3*(size_t)NR*Dd;

    init_kernel<<<64, 256>>>();
    proj_kernel<<<dim3(4, 256, 4), 256>>>(v_fea, a_fea, Wv1, Wv2, Wa1, Wa2);
    score_kernel<<<dim3(32, 32, 8), 256>>>();
    row_mask_kernel<<<NR, 256>>>(thr_p);
    col_partial_kernel<<<dim3(8, 8, 8), 256>>>(thr_p);
    col_finalize_kernel<<<64, 256>>>(thr_p);
    pred_kernel<<<8, 256>>>(out_pred);
    apply_va_kernel<<<dim3(4, 32, 8), 256>>>();
    apply_av_kernel<<<dim3(4, 32, 8), 256>>>();
    fc_kernel<<<dim3(4, 256, 2), 256>>>(v_fea, a_fea, Wvfc, Wafc);
    ln_fuse_kernel<<<NR, 256>>>(ln_g, ln_b, out_fuse, out_vpsp, out_apsp);
}

// round 2
// speedup vs baseline: 1.0586x; 1.0586x over previous
#include <cuda_runtime.h>

// Problem constants (fixed shapes)
#define Bx 8
#define Tt 2048
#define Dd 256
#define NR (Bx*Tt)            // 16384 rows
#define EPSF 1e-8f

// ---------------- scratch (device globals; no runtime allocation) ----------
__device__ float g_v1[(size_t)NR*Dd];
__device__ float g_v2[(size_t)NR*Dd];
__device__ float g_a1[(size_t)NR*Dd];
__device__ float g_a2[(size_t)NR*Dd];
__device__ float g_beta[(size_t)Bx*Tt*Tt];   // 134 MB
__device__ float g_R[Bx*Tt];       // row sums of beta
__device__ float g_Cc[Bx*Tt];      // col sums of beta
__device__ float g_SmC[Bx*Tt];     // masked col sums (atomic accum)
__device__ float g_thrR[Bx*Tt];
__device__ float g_scaleR[Bx*Tt];
__device__ float g_thrC[Bx*Tt];
__device__ float g_scaleC[Bx*Tt];
__device__ float g_apos[(size_t)NR*Dd];
__device__ float g_vpos[(size_t)NR*Dd];
__device__ float g_zv[(size_t)NR*Dd];
__device__ float g_za[(size_t)NR*Dd];

// ---------------- helpers ---------------------------------------------------
__device__ __forceinline__ void mm_tile_16(const float Xs[16][64], const float Ws[16][64],
                                           float acc[4][4], int tx, int ty) {
#pragma unroll
    for (int kk = 0; kk < 16; kk++) {
        float4 a4 = *reinterpret_cast<const float4*>(&Xs[kk][ty*4]);
        float4 b4 = *reinterpret_cast<const float4*>(&Ws[kk][tx*4]);
        float a[4] = {a4.x, a4.y, a4.z, a4.w};
        float b[4] = {b4.x, b4.y, b4.z, b4.w};
#pragma unroll
        for (int i = 0; i < 4; i++)
#pragma unroll
            for (int j = 0; j < 4; j++) acc[i][j] += a[i]*b[j];
    }
}

// ---------------- init: zero accumulators -----------------------------------
__global__ void init_kernel() {
    int idx = blockIdx.x*256 + threadIdx.x;
    if (idx < Bx*Tt) { g_R[idx] = 0.f; g_Cc[idx] = 0.f; g_SmC[idx] = 0.f; }
}

// ---------------- K1: 4 projection GEMMs + ReLU ------------------------------
// C[n,h] = relu(sum_d X[n,d] * W[h,d]);  M=16384, N=256, K=256
__global__ void proj_kernel(const float* __restrict__ v_fea, const float* __restrict__ a_fea,
                            const float* __restrict__ Wv1, const float* __restrict__ Wv2,
                            const float* __restrict__ Wa1, const float* __restrict__ Wa2) {
    int which = blockIdx.z;
    const float* X = (which < 2) ? v_fea : a_fea;
    const float* W = (which == 0) ? Wv1 : (which == 1) ? Wv2 : (which == 2) ? Wa1 : Wa2;
    float* Cout = (which == 0) ? g_v1 : (which == 1) ? g_v2 : (which == 2) ? g_a1 : g_a2;

    __shared__ float Xs[16][64];
    __shared__ float Ws[16][64];
    int bm = blockIdx.y*64, bn = blockIdx.x*64;
    int tid = threadIdx.x, tx = tid % 16, ty = tid / 16;
    float acc[4][4] = {};
    for (int k0 = 0; k0 < Dd; k0 += 16) {
#pragma unroll
        for (int r = 0; r < 4; r++) {
            int kk = tid % 16, mm = tid / 16 + r*16;
            Xs[kk][mm] = X[(size_t)(bm+mm)*Dd + k0 + kk];
            Ws[kk][mm] = W[(size_t)(bn+mm)*Dd + k0 + kk];
        }
        __syncthreads();
        mm_tile_16(Xs, Ws, acc, tx, ty);
        __syncthreads();
    }
#pragma unroll
    for (int i = 0; i < 4; i++) {
        float4 v;
        v.x = fmaxf(acc[i][0], 0.f); v.y = fmaxf(acc[i][1], 0.f);
        v.z = fmaxf(acc[i][2], 0.f); v.w = fmaxf(acc[i][3], 0.f);
        *reinterpret_cast<float4*>(&Cout[(size_t)(bm + ty*4 + i)*Dd + bn + tx*4]) = v;
    }
}

// ---------------- K2: score GEMM beta = relu(v2 @ a1^T / 16) + row/col sums --
__global__ void score_kernel() {
    int b = blockIdx.z;
    const float* V2 = g_v2 + (size_t)b*Tt*Dd;
    const float* A1 = g_a1 + (size_t)b*Tt*Dd;
    float* beta = g_beta + (size_t)b*Tt*Tt;

    __shared__ float Xs[16][64];
    __shared__ float Ws[16][64];
    __shared__ float srow[64], scol[64];
    int bm = blockIdx.y*64, bn = blockIdx.x*64;
    int tid = threadIdx.x, tx = tid % 16, ty = tid / 16;
    if (tid < 64) { srow[tid] = 0.f; scol[tid] = 0.f; }
    float acc[4][4] = {};
    for (int k0 = 0; k0 < Dd; k0 += 16) {
#pragma unroll
        for (int r = 0; r < 4; r++) {
            int kk = tid % 16, mm = tid / 16 + r*16;
            Xs[kk][mm] = V2[(size_t)(bm+mm)*Dd + k0 + kk];
            Ws[kk][mm] = A1[(size_t)(bn+mm)*Dd + k0 + kk];
        }
        __syncthreads();
        mm_tile_16(Xs, Ws, acc, tx, ty);
        __syncthreads();
    }
    float vals[4][4];
    float rsum[4] = {0,0,0,0}, csum[4] = {0,0,0,0};
#pragma unroll
    for (int i = 0; i < 4; i++)
#pragma unroll
        for (int j = 0; j < 4; j++) {
            float v = fmaxf(acc[i][j]*(1.f/16.f), 0.f);
            vals[i][j] = v; rsum[i] += v; csum[j] += v;
        }
#pragma unroll
    for (int i = 0; i < 4; i++) {
        float4 v = {vals[i][0], vals[i][1], vals[i][2], vals[i][3]};
        *reinterpret_cast<float4*>(&beta[(size_t)(bm + ty*4 + i)*Tt + bn + tx*4]) = v;
        atomicAdd(&srow[ty*4 + i], rsum[i]);
        atomicAdd(&scol[tx*4 + i], csum[i]);
    }
    __syncthreads();
    if (tid < 64) {
        atomicAdd(&g_R[b*Tt + bm + tid], srow[tid]);
        atomicAdd(&g_Cc[b*Tt + bn + tid], scol[tid]);
    }
}

// ---------------- K3a: per-row masked sums -> thrR, scaleR --------------------
__global__ void row_mask_kernel(const float* __restrict__ thr_p) {
    int row = blockIdx.x;                  // 0..16383 (b*T + i)
    const float* brow = g_beta + (size_t)row*Tt;
    float thr = thr_p[0] * 10.f / (float)Tt;
    float R = g_R[row];
    float cut = thr * (R + EPSF);
    float s = 0.f;
    for (int j = threadIdx.x; j < Tt; j += 256) {
        float v = brow[j];
        if (v > cut) s += v;
    }
#pragma unroll
    for (int o = 16; o > 0; o >>= 1) s += __shfl_down_sync(0xffffffffu, s, o);
    __shared__ float sh[8];
    if ((threadIdx.x & 31) == 0) sh[threadIdx.x >> 5] = s;
    __syncthreads();
    if (threadIdx.x == 0) {
        float t = 0.f;
#pragma unroll
        for (int w = 0; w < 8; w++) t += sh[w];
        g_thrR[row] = cut;
        g_scaleR[row] = 1.f / (t + EPSF*(R + EPSF));
    }
}

// ---------------- K3b: per-col masked partial sums ---------------------------
__global__ void col_partial_kernel(const float* __restrict__ thr_p) {
    int b = blockIdx.z;
    int j = blockIdx.x*256 + threadIdx.x;
    int i0 = blockIdx.y*256;
    float thr = thr_p[0] * 10.f / (float)Tt;
    float Cv = g_Cc[b*Tt + j];
    float cut = thr * (Cv + EPSF);
    const float* bb = g_beta + (size_t)b*Tt*Tt;
    float s = 0.f;
#pragma unroll 4
    for (int i = i0; i < i0 + 256; i++) {
        float v = bb[(size_t)i*Tt + j];
        if (v > cut) s += v;
    }
    atomicAdd(&g_SmC[b*Tt + j], s);
}

__global__ void col_finalize_kernel(const float* __restrict__ thr_p) {
    int idx = blockIdx.x*256 + threadIdx.x;
    if (idx < Bx*Tt) {
        float thr = thr_p[0] * 10.f / (float)Tt;
        float Cv = g_Cc[idx];
        float cut = thr * (Cv + EPSF);
        g_thrC[idx] = cut;
        g_scaleC[idx] = 1.f / (g_SmC[idx] + EPSF*(Cv + EPSF));
    }
}

// ---------------- pred: diag of g_av[0] > 0 ----------------------------------
__global__ void pred_kernel(float* __restrict__ out_pred) {
    int t = blockIdx.x*256 + threadIdx.x;   // 0..2047
    float v = g_beta[(size_t)t*Tt + t];     // batch 0
    out_pred[t] = (v > g_thrC[t]) ? 1.f : 0.f;
}

// ---------------- K4a: a_pos = g_va @ a2 (mask applied on the fly) -----------
__global__ void apply_va_kernel() {
    int b = blockIdx.z;
    const float* beta = g_beta + (size_t)b*Tt*Tt;
    const float* Bm = g_a2 + (size_t)b*Tt*Dd;
    float* out = g_apos + (size_t)b*Tt*Dd;
    __shared__ float As[16][64];
    __shared__ float Bs[16][64];
    __shared__ float sThr[64], sScale[64];
    int bm = blockIdx.y*64, bn = blockIdx.x*64;
    int tid = threadIdx.x, tx = tid % 16, ty = tid / 16;
    if (tid < 64) { sThr[tid] = g_thrR[b*Tt + bm + tid]; sScale[tid] = g_scaleR[b*Tt + bm + tid]; }
    __syncthreads();
    float acc[4][4] = {};
    for (int k0 = 0; k0 < Tt; k0 += 16) {
#pragma unroll
        for (int r = 0; r < 4; r++) {
            int kk = tid % 16, mm = tid / 16 + r*16;
            float v = beta[(size_t)(bm+mm)*Tt + k0 + kk];
            As[kk][mm] = (v > sThr[mm]) ? v * sScale[mm] : 0.f;
            int nn = tid % 64, k2 = tid / 64 + r*4;
            Bs[k2][nn] = Bm[(size_t)(k0+k2)*Dd + bn + nn];
        }
        __syncthreads();
        mm_tile_16(As, Bs, acc, tx, ty);
        __syncthreads();
    }
#pragma unroll
    for (int i = 0; i < 4; i++) {
        float4 v = {acc[i][0], acc[i][1], acc[i][2], acc[i][3]};
        *reinterpret_cast<float4*>(&out[(size_t)(bm + ty*4 + i)*Dd + bn + tx*4]) = v;
    }
}

// ---------------- K4b: v_pos = g_av @ v1 (A = masked beta^T) ------------------
__global__ void apply_av_kernel() {
    int b = blockIdx.z;
    const float* beta = g_beta + (size_t)b*Tt*Tt;
    const float* Bm = g_v1 + (size_t)b*Tt*Dd;
    float* out = g_vpos + (size_t)b*Tt*Dd;
    __shared__ float As[16][64];
    __shared__ float Bs[16][64];
    __shared__ float sThr[64], sScale[64];
    int bm = blockIdx.y*64, bn = blockIdx.x*64;
    int tid = threadIdx.x, tx = tid % 16, ty = tid / 16;
    if (tid < 64) { sThr[tid] = g_thrC[b*Tt + bm + tid]; sScale[tid] = g_scaleC[b*Tt + bm + tid]; }
    __syncthreads();
    float acc[4][4] = {};
    for (int k0 = 0; k0 < Tt; k0 += 16) {
#pragma unroll
        for (int r = 0; r < 4; r++) {
            int mm = tid % 64, kk = tid / 64 + r*4;   // transposed read, coalesced over mm
            float v = beta[(size_t)(k0+kk)*Tt + bm + mm];
            As[kk][mm] = (v > sThr[mm]) ? v * sScale[mm] : 0.f;
            int nn = tid % 64, k2 = tid / 64 + r*4;
            Bs[k2][nn] = Bm[(size_t)(k0+k2)*Dd + bn + nn];
        }
        __syncthreads();
        mm_tile_16(As, Bs, acc, tx, ty);
        __syncthreads();
    }
#pragma unroll
    for (int i = 0; i < 4; i++) {
        float4 v = {acc[i][0], acc[i][1], acc[i][2], acc[i][3]};
        *reinterpret_cast<float4*>(&out[(size_t)(bm + ty*4 + i)*Dd + bn + tx*4]) = v;
    }
}

// ---------------- K5: z = relu((X1 + X2) @ W^T) ------------------------------
__global__ void fc_kernel(const float* __restrict__ v_fea, const float* __restrict__ a_fea,
                          const float* __restrict__ Wvfc, const float* __restrict__ Wafc) {
    int which = blockIdx.z;       // 0: v branch, 1: a branch
    const float* X1 = (which == 0) ? v_fea : a_fea;
    const float* X2 = (which == 0) ? g_apos : g_vpos;
    const float* W  = (which == 0) ? Wvfc : Wafc;
    float* Cout     = (which == 0) ? g_zv : g_za;

    __shared__ float Xs[16][64];
    __shared__ float Ws[16][64];
    int bm = blockIdx.y*64, bn = blockIdx.x*64;
    int tid = threadIdx.x, tx = tid % 16, ty = tid / 16;
    float acc[4][4] = {};
    for (int k0 = 0; k0 < Dd; k0 += 16) {
#pragma unroll
        for (int r = 0; r < 4; r++) {
            int kk = tid % 16, mm = tid / 16 + r*16;
            size_t xi = (size_t)(bm+mm)*Dd + k0 + kk;
            Xs[kk][mm] = X1[xi] + X2[xi];
            Ws[kk][mm] = W[(size_t)(bn+mm)*Dd + k0 + kk];
        }
        __syncthreads();
        mm_tile_16(Xs, Ws, acc, tx, ty);
        __syncthreads();
    }
#pragma unroll
    for (int i = 0; i < 4; i++) {
        float4 v;
        v.x = fmaxf(acc[i][0], 0.f); v.y = fmaxf(acc[i][1], 0.f);
        v.z = fmaxf(acc[i][2], 0.f); v.w = fmaxf(acc[i][3], 0.f);
        *reinterpret_cast<float4*>(&Cout[(size_t)(bm + ty*4 + i)*Dd + bn + tx*4]) = v;
    }
}

// ---------------- K6: dual LayerNorm + fuse ----------------------------------
__global__ void ln_fuse_kernel(const float* __restrict__ ln_g, const float* __restrict__ ln_b,
                               float* __restrict__ out_fuse, float* __restrict__ out_vpsp,
                               float* __restrict__ out_apsp) {
    int row = blockIdx.x;          // 0..16383
    int tid = threadIdx.x;         // 0..255 == feature index
    float zv = g_zv[(size_t)row*Dd + tid];
    float za = g_za[(size_t)row*Dd + tid];
    float4 s = make_float4(zv, zv*zv, za, za*za);
#pragma unroll
    for (int o = 16; o > 0; o >>= 1) {
        s.x += __shfl_down_sync(0xffffffffu, s.x, o);
        s.y += __shfl_down_sync(0xffffffffu, s.y, o);
        s.z += __shfl_down_sync(0xffffffffu, s.z, o);
        s.w += __shfl_down_sync(0xffffffffu, s.w, o);
    }
    __shared__ float4 sh[8];
    __shared__ float4 stats;
    if ((tid & 31) == 0) sh[tid >> 5] = s;
    __syncthreads();
    if (tid == 0) {
        float4 t = sh[0];
#pragma unroll
        for (int w = 1; w < 8; w++) { t.x += sh[w].x; t.y += sh[w].y; t.z += sh[w].z; t.w += sh[w].w; }
        stats = t;
    }
    __syncthreads();
    float inv = 1.f / (float)Dd;
    float mv = stats.x * inv, mva = stats.z * inv;
    float varv = stats.y * inv - mv*mv;
    float vara = stats.w * inv - mva*mva;
    float g = ln_g[tid], bb = ln_b[tid];
    float vpsp = (zv - mv) * rsqrtf(varv + 1e-6f) * g + bb;
    float apsp = (za - mva) * rsqrtf(vara + 1e-6f) * g + bb;
    size_t o = (size_t)row*Dd + tid;
    out_vpsp[o] = vpsp;
    out_apsp[o] = apsp;
    out_fuse[o] = 0.5f * (vpsp + apsp);
}

// ---------------- launch ------------------------------------------------------
extern "C" void kernel_launch(void* const* d_in, const int* in_sizes, int n_in,
                              void* d_out, int out_size) {
    const float* a_fea = (const float*)d_in[0];
    const float* v_fea = (const float*)d_in[1];
    const float* thr_p = (const float*)d_in[2];
    const float* Wv1   = (const float*)d_in[3];
    const float* Wv2   = (const float*)d_in[4];
    const float* Wvfc  = (const float*)d_in[5];
    const float* Wa1   = (const float*)d_in[6];
    const float* Wa2   = (const float*)d_in[7];
    const float* Wafc  = (const float*)d_in[8];
    const float* ln_g  = (const float*)d_in[9];
    const float* ln_b  = (const float*)d_in[10];
    (void)in_sizes; (void)n_in; (void)out_size;

    float* out = (float*)d_out;
    float* out_fuse = out;
    float* out_vpsp = out + (size_t)NR*Dd;
    float* out_apsp = out + 2*(size_t)NR*Dd;
    float* out_pred = out + 3*(size_t)NR*Dd;

    init_kernel<<<64, 256>>>();
    proj_kernel<<<dim3(4, 256, 4), 256>>>(v_fea, a_fea, Wv1, Wv2, Wa1, Wa2);
    score_kernel<<<dim3(32, 32, 8), 256>>>();
    row_mask_kernel<<<NR, 256>>>(thr_p);
    col_partial_kernel<<<dim3(8, 8, 8), 256>>>(thr_p);
    col_finalize_kernel<<<64, 256>>>(thr_p);
    pred_kernel<<<8, 256>>>(out_pred);
    apply_va_kernel<<<dim3(4, 32, 8), 256>>>();
    apply_av_kernel<<<dim3(4, 32, 8), 256>>>();
    fc_kernel<<<dim3(4, 256, 2), 256>>>(v_fea, a_fea, Wvfc, Wafc);
    ln_fuse_kernel<<<NR, 256>>>(ln_g, ln_b, out_fuse, out_vpsp, out_apsp);
}

// round 3
// speedup vs baseline: 3.3551x; 3.1695x over previous
#include <cuda_runtime.h>
#include <cstdint>

// Problem constants (fixed shapes)
#define Bx 8
#define Tt 2048
#define Dd 256
#define NR (Bx*Tt)            // 16384 rows
#define EPSF 1e-8f

// GEMM tiling
#define BM 128
#define BN 128
#define BK 16
#define LDW 132               // padded shared row (floats)

// ---------------- scratch (device globals; no runtime allocation) ----------
__device__ float g_v1[(size_t)NR*Dd];
__device__ float g_v2[(size_t)NR*Dd];
__device__ float g_a1[(size_t)NR*Dd];
__device__ float g_a2[(size_t)NR*Dd];
__device__ float g_beta[(size_t)Bx*Tt*Tt];   // 134 MB
__device__ float g_R[NR];        // row sums of beta
__device__ float g_Cc[NR];       // col sums of beta
__device__ float g_SmR[NR];      // masked row sums
__device__ float g_SmC[NR];      // masked col sums
__device__ float g_thrR[NR];
__device__ float g_scaleR[NR];
__device__ float g_thrC[NR];
__device__ float g_scaleC[NR];
__device__ float g_apos[(size_t)NR*Dd];
__device__ float g_vpos[(size_t)NR*Dd];
__device__ float g_zv[(size_t)NR*Dd];
__device__ float g_za[(size_t)NR*Dd];

// ---------------- tf32 helpers ----------------------------------------------
__device__ __forceinline__ float to_tf32(float x){
    uint32_t u; asm("cvt.rna.tf32.f32 %0, %1;" : "=r"(u) : "f"(x));
    return __uint_as_float(u);
}

__device__ __forceinline__ void mma8(float4& d, const uint32_t* a, const uint32_t* b){
    asm volatile("mma.sync.aligned.m16n8k8.row.col.f32.tf32.tf32.f32 "
        "{%0,%1,%2,%3}, {%4,%5,%6,%7}, {%8,%9}, {%0,%1,%2,%3};"
        : "+f"(d.x), "+f"(d.y), "+f"(d.z), "+f"(d.w)
        : "r"(a[0]), "r"(a[1]), "r"(a[2]), "r"(a[3]), "r"(b[0]), "r"(b[1]));
}

// compute one 128x128x16 tile: warp tile 32x64 (2 m-atoms x 8 n-atoms)
__device__ __forceinline__ void compute_tile(const float A[BK][LDW], const float Bsh[BK][LDW],
                                             float4 d[2][8], int wm, int wn, int lr, int lc){
#pragma unroll
    for (int ks = 0; ks < BK; ks += 8){
        uint32_t a[2][4];
#pragma unroll
        for (int mi = 0; mi < 2; mi++){
            int m0 = wm + mi*16 + lr;
            a[mi][0] = __float_as_uint(A[ks+lc  ][m0  ]);
            a[mi][1] = __float_as_uint(A[ks+lc  ][m0+8]);
            a[mi][2] = __float_as_uint(A[ks+lc+4][m0  ]);
            a[mi][3] = __float_as_uint(A[ks+lc+4][m0+8]);
        }
        uint32_t b[8][2];
#pragma unroll
        for (int ni = 0; ni < 8; ni++){
            int n0 = wn + ni*8 + lr;
            b[ni][0] = __float_as_uint(Bsh[ks+lc  ][n0]);
            b[ni][1] = __float_as_uint(Bsh[ks+lc+4][n0]);
        }
#pragma unroll
        for (int mi = 0; mi < 2; mi++)
#pragma unroll
            for (int ni = 0; ni < 8; ni++) mma8(d[mi][ni], a[mi], b[ni]);
    }
}

// ---- staging: row-major source (128 rows x 16 k), transposed to k-major smem
__device__ __forceinline__ void ldg_rm(float4 v[2], const float* __restrict__ src, int ld, int t){
    int kk4 = (t & 3) * 4, mm = t >> 2;
    v[0] = *reinterpret_cast<const float4*>(src + (size_t)mm*ld + kk4);
    v[1] = *reinterpret_cast<const float4*>(src + (size_t)(mm+64)*ld + kk4);
}
__device__ __forceinline__ void ldg_rm2(float4 v[2], const float* __restrict__ s1,
                                        const float* __restrict__ s2, int ld, int t){
    int kk4 = (t & 3) * 4, mm = t >> 2;
#pragma unroll
    for (int i = 0; i < 2; i++){
        float4 a = *reinterpret_cast<const float4*>(s1 + (size_t)(mm+i*64)*ld + kk4);
        float4 b = *reinterpret_cast<const float4*>(s2 + (size_t)(mm+i*64)*ld + kk4);
        v[i].x = a.x+b.x; v[i].y = a.y+b.y; v[i].z = a.z+b.z; v[i].w = a.w+b.w;
    }
}
__device__ __forceinline__ void sts_rm(float S[BK][LDW], const float4 v[2], int t){
    int kk4 = (t & 3) * 4, mm = t >> 2;
#pragma unroll
    for (int i = 0; i < 2; i++){
        S[kk4+0][mm+i*64] = to_tf32(v[i].x);
        S[kk4+1][mm+i*64] = to_tf32(v[i].y);
        S[kk4+2][mm+i*64] = to_tf32(v[i].z);
        S[kk4+3][mm+i*64] = to_tf32(v[i].w);
    }
}
// masked variant (row mask; thread owns rows mm and mm+64 for the whole kernel)
__device__ __forceinline__ void sts_rm_mask(float S[BK][LDW], const float4 v[2],
                                            float thr0, float scl0, float thr1, float scl1, int t){
    int kk4 = (t & 3) * 4, mm = t >> 2;
    const float4 a = v[0];
    S[kk4+0][mm] = to_tf32(a.x > thr0 ? a.x*scl0 : 0.f);
    S[kk4+1][mm] = to_tf32(a.y > thr0 ? a.y*scl0 : 0.f);
    S[kk4+2][mm] = to_tf32(a.z > thr0 ? a.z*scl0 : 0.f);
    S[kk4+3][mm] = to_tf32(a.w > thr0 ? a.w*scl0 : 0.f);
    const float4 c = v[1];
    S[kk4+0][mm+64] = to_tf32(c.x > thr1 ? c.x*scl1 : 0.f);
    S[kk4+1][mm+64] = to_tf32(c.y > thr1 ? c.y*scl1 : 0.f);
    S[kk4+2][mm+64] = to_tf32(c.z > thr1 ? c.z*scl1 : 0.f);
    S[kk4+3][mm+64] = to_tf32(c.w > thr1 ? c.w*scl1 : 0.f);
}
// ---- staging: k-major source (16 k-rows x 128 cols), direct to k-major smem
__device__ __forceinline__ void ldg_km(float4 v[2], const float* __restrict__ src, int ld, int t){
    int nn4 = (t & 31) * 4, kk = t >> 5;
    v[0] = *reinterpret_cast<const float4*>(src + (size_t)kk*ld + nn4);
    v[1] = *reinterpret_cast<const float4*>(src + (size_t)(kk+8)*ld + nn4);
}
__device__ __forceinline__ void sts_km(float S[BK][LDW], const float4 v[2], int t){
    int nn4 = (t & 31) * 4, kk = t >> 5;
#pragma unroll
    for (int i = 0; i < 2; i++){
        float4 c;
        c.x = to_tf32(v[i].x); c.y = to_tf32(v[i].y);
        c.z = to_tf32(v[i].z); c.w = to_tf32(v[i].w);
        *reinterpret_cast<float4*>(&S[kk+i*8][nn4]) = c;
    }
}
// masked k-major (col mask varies within float4)
__device__ __forceinline__ void sts_km_mask(float S[BK][LDW], const float4 v[2],
                                            const float4 thr, const float4 scl, int t){
    int nn4 = (t & 31) * 4, kk = t >> 5;
#pragma unroll
    for (int i = 0; i < 2; i++){
        float4 c;
        c.x = to_tf32(v[i].x > thr.x ? v[i].x*scl.x : 0.f);
        c.y = to_tf32(v[i].y > thr.y ? v[i].y*scl.y : 0.f);
        c.z = to_tf32(v[i].z > thr.z ? v[i].z*scl.z : 0.f);
        c.w = to_tf32(v[i].w > thr.w ? v[i].w*scl.w : 0.f);
        *reinterpret_cast<float4*>(&S[kk+i*8][nn4]) = c;
    }
}

__device__ __forceinline__ void zero_acc(float4 d[2][8]){
#pragma unroll
    for (int mi = 0; mi < 2; mi++)
#pragma unroll
        for (int ni = 0; ni < 8; ni++) d[mi][ni] = make_float4(0.f,0.f,0.f,0.f);
}

// ---------------- init: zero accumulators -----------------------------------
__global__ void init_kernel() {
    int idx = blockIdx.x*256 + threadIdx.x;
    if (idx < NR) { g_R[idx]=0.f; g_Cc[idx]=0.f; g_SmR[idx]=0.f; g_SmC[idx]=0.f; }
}

// ---------------- K1: 4 projection GEMMs + ReLU (tf32 mma) -------------------
__global__ void __launch_bounds__(256) proj_kernel(const float* __restrict__ v_fea,
        const float* __restrict__ a_fea, const float* __restrict__ Wv1,
        const float* __restrict__ Wv2, const float* __restrict__ Wa1,
        const float* __restrict__ Wa2) {
    int which = blockIdx.z;
    const float* X = (which < 2) ? v_fea : a_fea;
    const float* W = (which == 0) ? Wv1 : (which == 1) ? Wv2 : (which == 2) ? Wa1 : Wa2;
    float* Cout = (which == 0) ? g_v1 : (which == 1) ? g_v2 : (which == 2) ? g_a1 : g_a2;

    __shared__ __align__(16) float As[2][BK][LDW];
    __shared__ __align__(16) float Bs[2][BK][LDW];
    int bm = blockIdx.y*BM, bn = blockIdx.x*BN;
    int t = threadIdx.x, wid = t >> 5, lane = t & 31, lr = lane >> 2, lc = lane & 3;
    int wm = (wid >> 1)*32, wn = (wid & 1)*64;
    const float* Abase = X + (size_t)bm*Dd;
    const float* Bbase = W + (size_t)bn*Dd;
    float4 d[2][8]; zero_acc(d);
    float4 ra[2], rb[2];
    ldg_rm(ra, Abase, Dd, t); ldg_rm(rb, Bbase, Dd, t);
    sts_rm(As[0], ra, t); sts_rm(Bs[0], rb, t);
    __syncthreads();
    const int KT = Dd/BK;
    for (int kt = 0; kt < KT; kt++){
        if (kt+1 < KT){
            ldg_rm(ra, Abase + (kt+1)*BK, Dd, t);
            ldg_rm(rb, Bbase + (kt+1)*BK, Dd, t);
        }
        compute_tile(As[kt&1], Bs[kt&1], d, wm, wn, lr, lc);
        if (kt+1 < KT){
            sts_rm(As[(kt+1)&1], ra, t); sts_rm(Bs[(kt+1)&1], rb, t);
            __syncthreads();
        }
    }
#pragma unroll
    for (int mi = 0; mi < 2; mi++){
        int r0 = bm + wm + mi*16 + lr;
#pragma unroll
        for (int ni = 0; ni < 8; ni++){
            int c = bn + wn + ni*8 + lc*2;
            float2 v0 = {fmaxf(d[mi][ni].x,0.f), fmaxf(d[mi][ni].y,0.f)};
            float2 v1 = {fmaxf(d[mi][ni].z,0.f), fmaxf(d[mi][ni].w,0.f)};
            *reinterpret_cast<float2*>(&Cout[(size_t)r0*Dd + c]) = v0;
            *reinterpret_cast<float2*>(&Cout[(size_t)(r0+8)*Dd + c]) = v1;
        }
    }
}

// ---------------- K2: score GEMM + relu + row/col sums (tf32 mma) ------------
__global__ void __launch_bounds__(256) score_kernel() {
    int b = blockIdx.z;
    int bm = blockIdx.y*BM, bn = blockIdx.x*BN;
    const float* Abase = g_v2 + (size_t)b*Tt*Dd + (size_t)bm*Dd;
    const float* Bbase = g_a1 + (size_t)b*Tt*Dd + (size_t)bn*Dd;
    float* beta = g_beta + (size_t)b*Tt*Tt;

    __shared__ __align__(16) float As[2][BK][LDW];
    __shared__ __align__(16) float Bs[2][BK][LDW];
    __shared__ float srow[BM], scol[BN];
    int t = threadIdx.x, wid = t >> 5, lane = t & 31, lr = lane >> 2, lc = lane & 3;
    int wm = (wid >> 1)*32, wn = (wid & 1)*64;
    if (t < 128){ srow[t] = 0.f; scol[t] = 0.f; }
    float4 d[2][8]; zero_acc(d);
    float4 ra[2], rb[2];
    ldg_rm(ra, Abase, Dd, t); ldg_rm(rb, Bbase, Dd, t);
    sts_rm(As[0], ra, t); sts_rm(Bs[0], rb, t);
    __syncthreads();
    const int KT = Dd/BK;
    for (int kt = 0; kt < KT; kt++){
        if (kt+1 < KT){
            ldg_rm(ra, Abase + (kt+1)*BK, Dd, t);
            ldg_rm(rb, Bbase + (kt+1)*BK, Dd, t);
        }
        compute_tile(As[kt&1], Bs[kt&1], d, wm, wn, lr, lc);
        if (kt+1 < KT){
            sts_rm(As[(kt+1)&1], ra, t); sts_rm(Bs[(kt+1)&1], rb, t);
            __syncthreads();
        }
    }
    // epilogue: relu(acc/16), write beta, accumulate row/col sums
    float rsum[2][2] = {{0.f,0.f},{0.f,0.f}};
    float csum[8][2];
#pragma unroll
    for (int ni = 0; ni < 8; ni++){ csum[ni][0] = 0.f; csum[ni][1] = 0.f; }
#pragma unroll
    for (int mi = 0; mi < 2; mi++){
        int r0 = bm + wm + mi*16 + lr;
#pragma unroll
        for (int ni = 0; ni < 8; ni++){
            int c = bn + wn + ni*8 + lc*2;
            float v0 = fmaxf(d[mi][ni].x*(1.f/16.f), 0.f);
            float v1 = fmaxf(d[mi][ni].y*(1.f/16.f), 0.f);
            float v2 = fmaxf(d[mi][ni].z*(1.f/16.f), 0.f);
            float v3 = fmaxf(d[mi][ni].w*(1.f/16.f), 0.f);
            *reinterpret_cast<float2*>(&beta[(size_t)r0*Tt + c])     = make_float2(v0, v1);
            *reinterpret_cast<float2*>(&beta[(size_t)(r0+8)*Tt + c]) = make_float2(v2, v3);
            rsum[mi][0] += v0 + v1; rsum[mi][1] += v2 + v3;
            csum[ni][0] += v0 + v2; csum[ni][1] += v1 + v3;
        }
    }
    // row sums: reduce across the 4 lanes sharing a row (lc), then shared atomic
#pragma unroll
    for (int mi = 0; mi < 2; mi++)
#pragma unroll
        for (int h = 0; h < 2; h++){
            float r = rsum[mi][h];
            r += __shfl_xor_sync(0xffffffffu, r, 1);
            r += __shfl_xor_sync(0xffffffffu, r, 2);
            if (lc == 0) atomicAdd(&srow[wm + mi*16 + h*8 + lr], r);
        }
    // col sums: shared atomics (4 warps contribute per column)
#pragma unroll
    for (int ni = 0; ni < 8; ni++){
        atomicAdd(&scol[wn + ni*8 + lc*2    ], csum[ni][0]);
        atomicAdd(&scol[wn + ni*8 + lc*2 + 1], csum[ni][1]);
    }
    __syncthreads();
    if (t < 128){
        atomicAdd(&g_R [b*Tt + bm + t], srow[t]);
        atomicAdd(&g_Cc[b*Tt + bn + t], scol[t]);
    }
}

// ---------------- thresholds -------------------------------------------------
__global__ void thresh_kernel(const float* __restrict__ thr_p) {
    int idx = blockIdx.x*256 + threadIdx.x;
    if (idx < NR){
        float thr = thr_p[0] * 10.f / (float)Tt;
        g_thrR[idx] = thr * (g_R[idx]  + EPSF);
        g_thrC[idx] = thr * (g_Cc[idx] + EPSF);
    }
}

// ---------------- fused masked row+col sums (single pass over beta) ----------
__global__ void mask_sums_kernel() {
    int b = blockIdx.z;
    int j4 = blockIdx.x*128 + (threadIdx.x & 31)*4;
    int w  = threadIdx.x >> 5;           // 0..7
    int i0 = blockIdx.y*1024;
    const float* bb = g_beta + (size_t)b*Tt*Tt;
    float4 thr = *reinterpret_cast<const float4*>(&g_thrC[b*Tt + j4]);
    float4 cs = make_float4(0.f,0.f,0.f,0.f);
    for (int i = i0 + w; i < i0 + 1024; i += 8){
        float4 v = *reinterpret_cast<const float4*>(bb + (size_t)i*Tt + j4);
        float thrR_i = g_thrR[b*Tt + i];
        float r = (v.x > thrR_i ? v.x : 0.f) + (v.y > thrR_i ? v.y : 0.f)
                + (v.z > thrR_i ? v.z : 0.f) + (v.w > thrR_i ? v.w : 0.f);
        cs.x += (v.x > thr.x ? v.x : 0.f);
        cs.y += (v.y > thr.y ? v.y : 0.f);
        cs.z += (v.z > thr.z ? v.z : 0.f);
        cs.w += (v.w > thr.w ? v.w : 0.f);
#pragma unroll
        for (int o = 16; o > 0; o >>= 1) r += __shfl_down_sync(0xffffffffu, r, o);
        if ((threadIdx.x & 31) == 0) atomicAdd(&g_SmR[b*Tt + i], r);
    }
    atomicAdd(&g_SmC[b*Tt + j4 + 0], cs.x);
    atomicAdd(&g_SmC[b*Tt + j4 + 1], cs.y);
    atomicAdd(&g_SmC[b*Tt + j4 + 2], cs.z);
    atomicAdd(&g_SmC[b*Tt + j4 + 3], cs.w);
}

__global__ void finalize_kernel() {
    int idx = blockIdx.x*256 + threadIdx.x;
    if (idx < NR){
        g_scaleR[idx] = 1.f / (g_SmR[idx] + EPSF*(g_R[idx]  + EPSF));
        g_scaleC[idx] = 1.f / (g_SmC[idx] + EPSF*(g_Cc[idx] + EPSF));
    }
}

__global__ void pred_kernel(float* __restrict__ out_pred) {
    int t = blockIdx.x*256 + threadIdx.x;   // 0..2047
    float v = g_beta[(size_t)t*Tt + t];     // batch 0
    out_pred[t] = (v > g_thrC[t]) ? 1.f : 0.f;
}

// ---------------- K4a: a_pos = g_va @ a2 (row mask on the fly, tf32) ---------
__global__ void __launch_bounds__(256) applyva_kernel() {
    int b = blockIdx.z;
    int bm = blockIdx.y*BM, bn = blockIdx.x*BN;
    const float* Abase = g_beta + (size_t)b*Tt*Tt + (size_t)bm*Tt;
    const float* Bbase = g_a2 + (size_t)b*Tt*Dd + bn;
    float* out = g_apos + (size_t)b*Tt*Dd;

    __shared__ __align__(16) float As[2][BK][LDW];
    __shared__ __align__(16) float Bs[2][BK][LDW];
    int t = threadIdx.x, wid = t >> 5, lane = t & 31, lr = lane >> 2, lc = lane & 3;
    int wm = (wid >> 1)*32, wn = (wid & 1)*64;
    int mm = t >> 2;
    float thr0 = g_thrR[b*Tt + bm + mm],      scl0 = g_scaleR[b*Tt + bm + mm];
    float thr1 = g_thrR[b*Tt + bm + mm + 64], scl1 = g_scaleR[b*Tt + bm + mm + 64];

    float4 d[2][8]; zero_acc(d);
    float4 ra[2], rb[2];
    ldg_rm(ra, Abase, Tt, t);
    ldg_km(rb, Bbase, Dd, t);
    sts_rm_mask(As[0], ra, thr0, scl0, thr1, scl1, t);
    sts_km(Bs[0], rb, t);
    __syncthreads();
    const int KT = Tt/BK;  // 128
    for (int kt = 0; kt < KT; kt++){
        if (kt+1 < KT){
            ldg_rm(ra, Abase + (kt+1)*BK, Tt, t);
            ldg_km(rb, Bbase + (size_t)(kt+1)*BK*Dd, Dd, t);
        }
        compute_tile(As[kt&1], Bs[kt&1], d, wm, wn, lr, lc);
        if (kt+1 < KT){
            sts_rm_mask(As[(kt+1)&1], ra, thr0, scl0, thr1, scl1, t);
            sts_km(Bs[(kt+1)&1], rb, t);
            __syncthreads();
        }
    }
#pragma unroll
    for (int mi = 0; mi < 2; mi++){
        int r0 = bm + wm + mi*16 + lr;
#pragma unroll
        for (int ni = 0; ni < 8; ni++){
            int c = bn + wn + ni*8 + lc*2;
            *reinterpret_cast<float2*>(&out[(size_t)r0*Dd + c])     = make_float2(d[mi][ni].x, d[mi][ni].y);
            *reinterpret_cast<float2*>(&out[(size_t)(r0+8)*Dd + c]) = make_float2(d[mi][ni].z, d[mi][ni].w);
        }
    }
}

// ---------------- K4b: v_pos = g_av @ v1 (A = masked beta^T, tf32) -----------
__global__ void __launch_bounds__(256) applyav_kernel() {
    int b = blockIdx.z;
    int bm = blockIdx.y*BM, bn = blockIdx.x*BN;
    const float* Abase = g_beta + (size_t)b*Tt*Tt + bm;   // column offset; rows are k
    const float* Bbase = g_v1 + (size_t)b*Tt*Dd + bn;
    float* out = g_vpos + (size_t)b*Tt*Dd;

    __shared__ __align__(16) float As[2][BK][LDW];
    __shared__ __align__(16) float Bs[2][BK][LDW];
    int t = threadIdx.x, wid = t >> 5, lane = t & 31, lr = lane >> 2, lc = lane & 3;
    int wm = (wid >> 1)*32, wn = (wid & 1)*64;
    int mm4 = (t & 31)*4;
    float4 thr4 = *reinterpret_cast<const float4*>(&g_thrC[b*Tt + bm + mm4]);
    float4 scl4 = *reinterpret_cast<const float4*>(&g_scaleC[b*Tt + bm + mm4]);

    float4 d[2][8]; zero_acc(d);
    float4 ra[2], rb[2];
    // transposed A load: A[m][k] = beta[k][m]; coalesced along m
    {
        int kk = t >> 5;
        ra[0] = *reinterpret_cast<const float4*>(Abase + (size_t)kk*Tt + mm4);
        ra[1] = *reinterpret_cast<const float4*>(Abase + (size_t)(kk+8)*Tt + mm4);
    }
    ldg_km(rb, Bbase, Dd, t);
    sts_km_mask(As[0], ra, thr4, scl4, t);
    sts_km(Bs[0], rb, t);
    __syncthreads();
    const int KT = Tt/BK;
    for (int kt = 0; kt < KT; kt++){
        if (kt+1 < KT){
            int kk = t >> 5;
            const float* p = Abase + (size_t)(kt+1)*BK*Tt;
            ra[0] = *reinterpret_cast<const float4*>(p + (size_t)kk*Tt + mm4);
            ra[1] = *reinterpret_cast<const float4*>(p + (size_t)(kk+8)*Tt + mm4);
            ldg_km(rb, Bbase + (size_t)(kt+1)*BK*Dd, Dd, t);
        }
        compute_tile(As[kt&1], Bs[kt&1], d, wm, wn, lr, lc);
        if (kt+1 < KT){
            sts_km_mask(As[(kt+1)&1], ra, thr4, scl4, t);
            sts_km(Bs[(kt+1)&1], rb, t);
            __syncthreads();
        }
    }
#pragma unroll
    for (int mi = 0; mi < 2; mi++){
        int r0 = bm + wm + mi*16 + lr;
#pragma unroll
        for (int ni = 0; ni < 8; ni++){
            int c = bn + wn + ni*8 + lc*2;
            *reinterpret_cast<float2*>(&out[(size_t)r0*Dd + c])     = make_float2(d[mi][ni].x, d[mi][ni].y);
            *reinterpret_cast<float2*>(&out[(size_t)(r0+8)*Dd + c]) = make_float2(d[mi][ni].z, d[mi][ni].w);
        }
    }
}

// ---------------- K5: z = relu((X1 + X2) @ W^T) (tf32) -----------------------
__global__ void __launch_bounds__(256) fc_kernel(const float* __restrict__ v_fea,
        const float* __restrict__ a_fea, const float* __restrict__ Wvfc,
        const float* __restrict__ Wafc) {
    int which = blockIdx.z;
    const float* X1 = (which == 0) ? v_fea : a_fea;
    const float* X2 = (which == 0) ? g_apos : g_vpos;
    const float* W  = (which == 0) ? Wvfc : Wafc;
    float* Cout     = (which == 0) ? g_zv : g_za;

    __shared__ __align__(16) float As[2][BK][LDW];
    __shared__ __align__(16) float Bs[2][BK][LDW];
    int bm = blockIdx.y*BM, bn = blockIdx.x*BN;
    int t = threadIdx.x, wid = t >> 5, lane = t & 31, lr = lane >> 2, lc = lane & 3;
    int wm = (wid >> 1)*32, wn = (wid & 1)*64;
    const float* A1 = X1 + (size_t)bm*Dd;
    const float* A2 = X2 + (size_t)bm*Dd;
    const float* Bbase = W + (size_t)bn*Dd;
    float4 d[2][8]; zero_acc(d);
    float4 ra[2], rb[2];
    ldg_rm2(ra, A1, A2, Dd, t); ldg_rm(rb, Bbase, Dd, t);
    sts_rm(As[0], ra, t); sts_rm(Bs[0], rb, t);
    __syncthreads();
    const int KT = Dd/BK;
    for (int kt = 0; kt < KT; kt++){
        if (kt+1 < KT){
            ldg_rm2(ra, A1 + (kt+1)*BK, A2 + (kt+1)*BK, Dd, t);
            ldg_rm(rb, Bbase + (kt+1)*BK, Dd, t);
        }
        compute_tile(As[kt&1], Bs[kt&1], d, wm, wn, lr, lc);
        if (kt+1 < KT){
            sts_rm(As[(kt+1)&1], ra, t); sts_rm(Bs[(kt+1)&1], rb, t);
            __syncthreads();
        }
    }
#pragma unroll
    for (int mi = 0; mi < 2; mi++){
        int r0 = bm + wm + mi*16 + lr;
#pragma unroll
        for (int ni = 0; ni < 8; ni++){
            int c = bn + wn + ni*8 + lc*2;
            float2 v0 = {fmaxf(d[mi][ni].x,0.f), fmaxf(d[mi][ni].y,0.f)};
            float2 v1 = {fmaxf(d[mi][ni].z,0.f), fmaxf(d[mi][ni].w,0.f)};
            *reinterpret_cast<float2*>(&Cout[(size_t)r0*Dd + c]) = v0;
            *reinterpret_cast<float2*>(&Cout[(size_t)(r0+8)*Dd + c]) = v1;
        }
    }
}

// ---------------- K6: dual LayerNorm + fuse ----------------------------------
__global__ void ln_fuse_kernel(const float* __restrict__ ln_g, const float* __restrict__ ln_b,
                               float* __restrict__ out_fuse, float* __restrict__ out_vpsp,
                               float* __restrict__ out_apsp) {
    int row = blockIdx.x;          // 0..16383
    int tid = threadIdx.x;         // 0..255 == feature index
    float zv = g_zv[(size_t)row*Dd + tid];
    float za = g_za[(size_t)row*Dd + tid];
    float4 s = make_float4(zv, zv*zv, za, za*za);
#pragma unroll
    for (int o = 16; o > 0; o >>= 1) {
        s.x += __shfl_down_sync(0xffffffffu, s.x, o);
        s.y += __shfl_down_sync(0xffffffffu, s.y, o);
        s.z += __shfl_down_sync(0xffffffffu, s.z, o);
        s.w += __shfl_down_sync(0xffffffffu, s.w, o);
    }
    __shared__ float4 sh[8];
    __shared__ float4 stats;
    if ((tid & 31) == 0) sh[tid >> 5] = s;
    __syncthreads();
    if (tid == 0) {
        float4 tt = sh[0];
#pragma unroll
        for (int w = 1; w < 8; w++) { tt.x += sh[w].x; tt.y += sh[w].y; tt.z += sh[w].z; tt.w += sh[w].w; }
        stats = tt;
    }
    __syncthreads();
    float inv = 1.f / (float)Dd;
    float mv = stats.x * inv, mva = stats.z * inv;
    float varv = stats.y * inv - mv*mv;
    float vara = stats.w * inv - mva*mva;
    float g = ln_g[tid], bb = ln_b[tid];
    float vpsp = (zv - mv) * rsqrtf(varv + 1e-6f) * g + bb;
    float apsp = (za - mva) * rsqrtf(vara + 1e-6f) * g + bb;
    size_t o = (size_t)row*Dd + tid;
    out_vpsp[o] = vpsp;
    out_apsp[o] = apsp;
    out_fuse[o] = 0.5f * (vpsp + apsp);
}

// ---------------- launch ------------------------------------------------------
extern "C" void kernel_launch(void* const* d_in, const int* in_sizes, int n_in,
                              void* d_out, int out_size) {
    const float* a_fea = (const float*)d_in[0];
    const float* v_fea = (const float*)d_in[1];
    const float* thr_p = (const float*)d_in[2];
    const float* Wv1   = (const float*)d_in[3];
    const float* Wv2   = (const float*)d_in[4];
    const float* Wvfc  = (const float*)d_in[5];
    const float* Wa1   = (const float*)d_in[6];
    const float* Wa2   = (const float*)d_in[7];
    const float* Wafc  = (const float*)d_in[8];
    const float* ln_g  = (const float*)d_in[9];
    const float* ln_b  = (const float*)d_in[10];
    (void)in_sizes; (void)n_in; (void)out_size;

    float* out = (float*)d_out;
    float* out_fuse = out;
    float* out_vpsp = out + (size_t)NR*Dd;
    float* out_apsp = out + 2*(size_t)NR*Dd;
    float* out_pred = out + 3*(size_t)NR*Dd;

    init_kernel<<<64, 256>>>();
    proj_kernel<<<dim3(Dd/BN, NR/BM, 4), 256>>>(v_fea, a_fea, Wv1, Wv2, Wa1, Wa2);
    score_kernel<<<dim3(Tt/BN, Tt/BM, Bx), 256>>>();
    thresh_kernel<<<64, 256>>>(thr_p);
    mask_sums_kernel<<<dim3(16, 2, Bx), 256>>>();
    finalize_kernel<<<64, 256>>>();
    pred_kernel<<<8, 256>>>(out_pred);
    applyva_kernel<<<dim3(Dd/BN, Tt/BM, Bx), 256>>>();
    applyav_kernel<<<dim3(Dd/BN, Tt/BM, Bx), 256>>>();
    fc_kernel<<<dim3(Dd/BN, NR/BM, 2), 256>>>(v_fea, a_fea, Wvfc, Wafc);
    ln_fuse_kernel<<<NR, 256>>>(ln_g, ln_b, out_fuse, out_vpsp, out_apsp);
}